// round 1
// baseline (speedup 1.0000x reference)
#include <cuda_runtime.h>
#include <cuda_bf16.h>
#include <math.h>

// Problem constants (fixed by the dataset)
#define NTOK 16384   // B*T = 4*4096
#define CDIM 1024
#define EXP  8
#define HDIM 4096

// ---------------- device scratch (no allocs allowed) ----------------
__device__ int   g_cnt[EXP];
__device__ int   g_tok[EXP * NTOK];
__device__ float g_prob[EXP * NTOK];
__device__ float g_h[(size_t)NTOK * HDIM];   // 256 MB activation scratch

// ---------------- init: zero out + counts ----------------
__global__ void init_kernel(float* out, int n_out) {
    int i = blockIdx.x * blockDim.x + threadIdx.x;
    int stride = gridDim.x * blockDim.x;
    for (int j = i; j < n_out; j += stride) out[j] = 0.0f;
    if (i < EXP) g_cnt[i] = 0;
}

// ---------------- routing: 1 warp per token ----------------
__global__ void route_kernel(const float* __restrict__ x,
                             const float* __restrict__ eps,
                             const float* __restrict__ rw,
                             const float* __restrict__ rb,
                             const float* __restrict__ nw,
                             const float* __restrict__ nb,
                             const int*   __restrict__ topk_p) {
    int warp = (blockIdx.x * blockDim.x + threadIdx.x) >> 5;
    int lane = threadIdx.x & 31;
    if (warp >= NTOK) return;

    const float* xr = x + (size_t)warp * CDIM;
    float ar[EXP], an[EXP];
#pragma unroll
    for (int e = 0; e < EXP; e++) { ar[e] = 0.f; an[e] = 0.f; }

    for (int j = lane; j < CDIM; j += 32) {
        float xv = xr[j];
        const float* rwj = rw + (size_t)j * EXP;
        const float* nwj = nw + (size_t)j * EXP;
#pragma unroll
        for (int e = 0; e < EXP; e++) {
            ar[e] = fmaf(xv, rwj[e], ar[e]);
            an[e] = fmaf(xv, nwj[e], an[e]);
        }
    }
#pragma unroll
    for (int e = 0; e < EXP; e++) {
#pragma unroll
        for (int o = 16; o > 0; o >>= 1) {
            ar[e] += __shfl_xor_sync(0xffffffffu, ar[e], o);
            an[e] += __shfl_xor_sync(0xffffffffu, an[e], o);
        }
    }

    if (lane == 0) {
        int k = *topk_p;
        if (k > EXP) k = EXP;
        float noisy[EXP];
#pragma unroll
        for (int e = 0; e < EXP; e++) {
            float z  = an[e] + nb[e];
            float sp = (z > 20.f) ? z : log1pf(expf(z));       // softplus
            noisy[e] = ar[e] + rb[e] + eps[(size_t)warp * EXP + e] * sp;
        }
        bool sel[EXP];
#pragma unroll
        for (int e = 0; e < EXP; e++) sel[e] = false;
        int idx[EXP];
        for (int t = 0; t < k; t++) {
            float best = -INFINITY; int bi = 0;
            for (int e = 0; e < EXP; e++)
                if (!sel[e] && noisy[e] > best) { best = noisy[e]; bi = e; }
            sel[bi] = true; idx[t] = bi;
        }
        float mx = -INFINITY;
        for (int t = 0; t < k; t++) mx = fmaxf(mx, noisy[idx[t]]);
        float den = 0.f;
        for (int t = 0; t < k; t++) den += expf(noisy[idx[t]] - mx);
        for (int t = 0; t < k; t++) {
            int e = idx[t];
            float p = expf(noisy[e] - mx) / den;
            int pos = atomicAdd(&g_cnt[e], 1);
            g_tok[e * NTOK + pos]  = warp;
            g_prob[e * NTOK + pos] = p;
        }
    }
}

// ---------------- tiled fp32 GEMM config ----------------
#define BM 128
#define BN 128
#define BK 16
#define TM 8
#define TN 8
// threads = (BM/TM)*(BN/TN) = 256

// GEMM1: h[r,:] = relu( x[tok[r],:] @ w1[e] + b1[e] )   (K = CDIM, N = HDIM)
__global__ __launch_bounds__(256)
void gemm1_kernel(const float* __restrict__ x,
                  const float* __restrict__ w1,
                  const float* __restrict__ b1,
                  int e) {
    __shared__ float As[BK][BM];
    __shared__ float Bs[BK][BN];
    __shared__ int   stok[BM];

    int count = g_cnt[e];
    int row0 = blockIdx.y * BM;
    if (row0 >= count) return;
    int col0 = blockIdx.x * BN;

    int tid = threadIdx.x;
    // cache token ids for this row tile
    if (tid < BM) {
        int r = row0 + tid;
        stok[tid] = (r < count) ? g_tok[e * NTOK + r] : 0;
    }
    __syncthreads();

    const float* W = w1 + (size_t)e * CDIM * HDIM;

    float acc[TM][TN];
#pragma unroll
    for (int i = 0; i < TM; i++)
#pragma unroll
        for (int j = 0; j < TN; j++) acc[i][j] = 0.f;

    int ty = tid >> 4;         // 0..15
    int tx = tid & 15;         // 0..15
    int rbase = ty * TM;
    int cbase = tx * TN;

    for (int k0 = 0; k0 < CDIM; k0 += BK) {
        // load A tile (gathered): 128x16 floats, float4 along k
        {
            // 512 float4 loads, 256 threads -> 2 each
#pragma unroll
            for (int it = 0; it < 2; it++) {
                int l = tid + it * 256;       // 0..511
                int m = l >> 2;               // row in tile
                int kq = (l & 3) * 4;         // k offset
                int t = stok[m];
                float4 v = *(const float4*)(x + (size_t)t * CDIM + k0 + kq);
                As[kq + 0][m] = v.x;
                As[kq + 1][m] = v.y;
                As[kq + 2][m] = v.z;
                As[kq + 3][m] = v.w;
            }
        }
        // load B tile: 16x128 floats
        {
#pragma unroll
            for (int it = 0; it < 2; it++) {
                int l = tid + it * 256;
                int k = l >> 5;               // 0..15
                int n = (l & 31) * 4;
                float4 v = *(const float4*)(W + (size_t)(k0 + k) * HDIM + col0 + n);
                *(float4*)&Bs[k][n] = v;
            }
        }
        __syncthreads();

#pragma unroll
        for (int k = 0; k < BK; k++) {
            float a[TM], b[TN];
            float4 a0 = *(float4*)&As[k][rbase];
            float4 a1 = *(float4*)&As[k][rbase + 4];
            a[0]=a0.x; a[1]=a0.y; a[2]=a0.z; a[3]=a0.w;
            a[4]=a1.x; a[5]=a1.y; a[6]=a1.z; a[7]=a1.w;
            float4 b0 = *(float4*)&Bs[k][cbase];
            float4 b1v = *(float4*)&Bs[k][cbase + 4];
            b[0]=b0.x; b[1]=b0.y; b[2]=b0.z; b[3]=b0.w;
            b[4]=b1v.x; b[5]=b1v.y; b[6]=b1v.z; b[7]=b1v.w;
#pragma unroll
            for (int i = 0; i < TM; i++)
#pragma unroll
                for (int j = 0; j < TN; j++)
                    acc[i][j] = fmaf(a[i], b[j], acc[i][j]);
        }
        __syncthreads();
    }

    // epilogue: relu(acc + b1), store to g_h
    const float* bias = b1 + (size_t)e * HDIM + col0;
#pragma unroll
    for (int i = 0; i < TM; i++) {
        int r = row0 + rbase + i;
        if (r >= count) continue;
        float* hrow = g_h + (size_t)r * HDIM + col0;
#pragma unroll
        for (int j = 0; j < TN; j++) {
            float v = acc[i][j] + bias[cbase + j];
            hrow[cbase + j] = v > 0.f ? v : 0.f;
        }
    }
}

// GEMM2: out[tok[r],:] += prob[r] * ( h[r,:] @ w2[e] + b2[e] )  (K = HDIM, N = CDIM)
__global__ __launch_bounds__(256)
void gemm2_kernel(const float* __restrict__ w2,
                  const float* __restrict__ b2,
                  float* __restrict__ out,
                  int e) {
    __shared__ float As[BK][BM];
    __shared__ float Bs[BK][BN];

    int count = g_cnt[e];
    int row0 = blockIdx.y * BM;
    if (row0 >= count) return;
    int col0 = blockIdx.x * BN;

    int tid = threadIdx.x;
    const float* W = w2 + (size_t)e * HDIM * CDIM;

    float acc[TM][TN];
#pragma unroll
    for (int i = 0; i < TM; i++)
#pragma unroll
        for (int j = 0; j < TN; j++) acc[i][j] = 0.f;

    int ty = tid >> 4;
    int tx = tid & 15;
    int rbase = ty * TM;
    int cbase = tx * TN;

    int rmax = count - row0;   // valid rows in this tile

    for (int k0 = 0; k0 < HDIM; k0 += BK) {
        // A tile from g_h (identity rows)
#pragma unroll
        for (int it = 0; it < 2; it++) {
            int l = tid + it * 256;
            int m = l >> 2;
            int kq = (l & 3) * 4;
            int r = (m < rmax) ? (row0 + m) : row0;  // clamp, guarded at store
            float4 v = *(const float4*)(g_h + (size_t)r * HDIM + k0 + kq);
            As[kq + 0][m] = v.x;
            As[kq + 1][m] = v.y;
            As[kq + 2][m] = v.z;
            As[kq + 3][m] = v.w;
        }
        // B tile from w2
#pragma unroll
        for (int it = 0; it < 2; it++) {
            int l = tid + it * 256;
            int k = l >> 5;
            int n = (l & 31) * 4;
            float4 v = *(const float4*)(W + (size_t)(k0 + k) * CDIM + col0 + n);
            *(float4*)&Bs[k][n] = v;
        }
        __syncthreads();

#pragma unroll
        for (int k = 0; k < BK; k++) {
            float a[TM], b[TN];
            float4 a0 = *(float4*)&As[k][rbase];
            float4 a1 = *(float4*)&As[k][rbase + 4];
            a[0]=a0.x; a[1]=a0.y; a[2]=a0.z; a[3]=a0.w;
            a[4]=a1.x; a[5]=a1.y; a[6]=a1.z; a[7]=a1.w;
            float4 b0 = *(float4*)&Bs[k][cbase];
            float4 b1v = *(float4*)&Bs[k][cbase + 4];
            b[0]=b0.x; b[1]=b0.y; b[2]=b0.z; b[3]=b0.w;
            b[4]=b1v.x; b[5]=b1v.y; b[6]=b1v.z; b[7]=b1v.w;
#pragma unroll
            for (int i = 0; i < TM; i++)
#pragma unroll
                for (int j = 0; j < TN; j++)
                    acc[i][j] = fmaf(a[i], b[j], acc[i][j]);
        }
        __syncthreads();
    }

    const float* bias = b2 + (size_t)e * CDIM + col0;
#pragma unroll
    for (int i = 0; i < TM; i++) {
        int r = row0 + rbase + i;
        if (r >= count) continue;
        int t = g_tok[e * NTOK + r];
        float p = g_prob[e * NTOK + r];
        float* orow = out + (size_t)t * CDIM + col0;
#pragma unroll
        for (int j = 0; j < TN; j++) {
            // experts are processed in sequential kernel launches -> no race
            orow[cbase + j] += p * (acc[i][j] + bias[cbase + j]);
        }
    }
}

// ---------------- launch ----------------
extern "C" void kernel_launch(void* const* d_in, const int* in_sizes, int n_in,
                              void* d_out, int out_size) {
    const float* x    = (const float*)d_in[0];   // [4,4096,1024]
    const float* eps  = (const float*)d_in[1];   // [4,4096,8]
    const float* rw   = (const float*)d_in[2];   // [1024,8]
    const float* rb   = (const float*)d_in[3];   // [8]
    const float* nw   = (const float*)d_in[4];   // [1024,8]
    const float* nb   = (const float*)d_in[5];   // [8]
    const float* w1   = (const float*)d_in[6];   // [8,1024,4096]
    const float* b1   = (const float*)d_in[7];   // [8,4096]
    const float* w2   = (const float*)d_in[8];   // [8,4096,1024]
    const float* b2   = (const float*)d_in[9];   // [8,1024]
    const int*   topk = (const int*)d_in[10];    // scalar

    float* out = (float*)d_out;

    // zero output + expert counts
    init_kernel<<<1024, 256>>>(out, out_size);

    // routing: 1 warp per token
    route_kernel<<<(NTOK * 32) / 256, 256>>>(x, eps, rw, rb, nw, nb, topk);

    // per-expert FFN (sequential on stream -> deterministic accumulation)
    dim3 g1(HDIM / BN, NTOK / BM);   // 32 x 128 (blocks beyond count exit)
    dim3 g2(CDIM / BN, NTOK / BM);   // 8 x 128
    for (int e = 0; e < EXP; e++) {
        gemm1_kernel<<<g1, 256>>>(x, w1, b1, e);
        gemm2_kernel<<<g2, 256>>>(w2, b2, out, e);
    }
}